// round 10
// baseline (speedup 1.0000x reference)
#include <cuda_runtime.h>
#include <stdint.h>

// Problem constants (fixed by the dataset)
#define NN     10000      // nodes
#define EE     1000       // hyperedges
#define TT     29         // STEPS - 1 transition steps
#define NROWS  (TT * EE)  // 29000 H rows
#define ROWCAP 64         // per-row nonzero capacity (Binom(10000,0.001): P(>64)~0)
#define NSIM   16         // persistent sim blocks (bids 0..15, scheduled first)
#define TPB    256
#define WPB    (TPB / 32)           // 8 warps per block
#define NEXT   (NROWS / WPB)        // 3625 extraction blocks: 1 warp = 1 row
#define NBLK   (NSIM + NEXT)
#define ROWF4  (NN / 4)   // 2500 uint4 per H row
#define CHUNK  4          // uint4 per lane per chunk (32*4 = 128 uint4/chunk)
#define NCHUNK 20         // chunks per row (20*128 = 2560 >= 2500)

// ---------------- device scratch (no allocations allowed) ----------------
__device__ unsigned short g_list[(size_t)NROWS * ROWCAP]; // node ids per row
__device__ unsigned g_rowcnt[NROWS];   // nonzeros per row
__device__ float    g_z[NN];           // z = H^T (H @ infected)
__device__ float    g_inf[NN];         // infected vector (0/1)
__device__ uint2    g_k1[TT];          // per-step uniform keys (u1)
__device__ uint2    g_k2[TT];          // per-step uniform keys (u2)
__device__ unsigned g_rows_done[TT];   // extraction progress per step (release flag)
__device__ unsigned g_bar_cnt;         // sim grid barrier: arrivals (monotonic)
__device__ unsigned g_bar_gen;         // sim grid barrier: released generation

// ---------------- JAX Threefry-2x32 (exact replica) ----------------
__device__ __forceinline__ void tf2x32(unsigned k0, unsigned k1,
                                       unsigned x0, unsigned x1,
                                       unsigned &o0, unsigned &o1) {
    unsigned ks2 = k0 ^ k1 ^ 0x1BD11BDAu;
    x0 += k0; x1 += k1;
#define ROTL(v,d) (((v) << (d)) | ((v) >> (32 - (d))))
#define RND(r) { x0 += x1; x1 = ROTL(x1, r); x1 ^= x0; }
    RND(13) RND(15) RND(26) RND(6)
    x0 += k1;  x1 += ks2 + 1u;
    RND(17) RND(29) RND(16) RND(24)
    x0 += ks2; x1 += k0 + 2u;
    RND(13) RND(15) RND(26) RND(6)
    x0 += k0;  x1 += k1 + 3u;
    RND(17) RND(29) RND(16) RND(24)
    x0 += k1;  x1 += ks2 + 4u;
    RND(13) RND(15) RND(26) RND(6)
    x0 += ks2; x1 += k0 + 5u;
    o0 = x0; o1 = x1;
#undef RND
#undef ROTL
}

__device__ __forceinline__ float bits_to_uniform(unsigned bits) {
    return __uint_as_float((bits >> 9) | 0x3F800000u) - 1.0f;
}

// ---------------- init: copy t=0 rows, key chain, reset all scratch ----------------
__global__ void k_init(const float* __restrict__ x, float* __restrict__ out) {
    int gid = blockIdx.x * blockDim.x + threadIdx.x;
    if (gid < NN * 3) {
        float v = x[gid];
        out[gid] = v;                                 // pathogen[0] = x
        out[(size_t)30 * NN * 3 + gid] = v;           // state[0]    = x
    }
    if (gid < NN) {
        g_z[gid]   = 0.0f;
        g_inf[gid] = x[gid * 3 + 1];
    }
    if (gid < TT) g_rows_done[gid] = 0u;
    if (gid == 0) {
        g_bar_cnt = 0u; g_bar_gen = 0u;
        // key chain: jax.random.key(42) -> (0, 42); partitionable split:
        // key_i = threefry(key, (0, i)) full output; new carry = i=0.
        unsigned kh = 0u, kl = 42u;
        for (int t = 0; t < TT; t++) {
            unsigned a0, a1, b0, b1, c0, c1;
            tf2x32(kh, kl, 0u, 0u, a0, a1);
            tf2x32(kh, kl, 0u, 1u, b0, b1);
            tf2x32(kh, kl, 0u, 2u, c0, c1);
            g_k1[t] = make_uint2(b0, b1);
            g_k2[t] = make_uint2(c0, c1);
            kh = a0; kl = a1;
        }
    }
}

// ---------------- sim-side grid barrier (NSIM blocks, sense counting) ----------------
__device__ __forceinline__ void sim_barrier(unsigned &gen) {
    __syncthreads();
    gen += 1u;
    if (threadIdx.x == 0) {
        __threadfence();                                   // release my writes
        unsigned a = atomicAdd(&g_bar_cnt, 1u) + 1u;
        if (a == gen * NSIM) {
            atomicExch(&g_bar_gen, gen);                   // release generation
        } else {
            while (atomicAdd(&g_bar_gen, 0u) < gen) __nanosleep(64);
        }
        __threadfence();                                   // acquire others' writes
    }
    __syncthreads();
}

// ---------------- producer role: one warp extracts one H row, then block exits --
// Non-persistent: extraction blocks never wait on anything, so waves just flow.
// Integer nonzero tests are exact (H bits are 0x0 or 0x3F800000).
__device__ void do_extract(const float* __restrict__ H) {
    const unsigned lane = threadIdx.x & 31u;
    const int r = (int)(blockIdx.x - NSIM) * WPB + (int)(threadIdx.x >> 5);
    // r in [0, NROWS): exact cover, one warp per row.

    const uint4* row = reinterpret_cast<const uint4*>(H + (size_t)r * NN);
    unsigned short* lp = g_list + (size_t)r * ROWCAP;
    unsigned cnt = 0u;   // warp-uniform

    for (int c = 0; c < NCHUNK; c++) {
        int b0 = c * (32 * CHUNK);
        uint4 buf[CHUNK];
#pragma unroll
        for (int k = 0; k < CHUNK; k++) {
            int idx = b0 + k * 32 + (int)lane;
            buf[k] = (idx < ROWF4) ? __ldg(row + idx) : make_uint4(0u, 0u, 0u, 0u);
        }
#pragma unroll
        for (int k = 0; k < CHUNK; k++) {
            uint4 v = buf[k];
            bool any = (v.x | v.y | v.z | v.w) != 0u;
            if (__ballot_sync(0xffffffffu, any) == 0u) continue;   // ~88% skip
            int idx4 = (b0 + k * 32 + (int)lane) * 4;
            unsigned vv[4] = {v.x, v.y, v.z, v.w};
#pragma unroll
            for (int cc = 0; cc < 4; cc++) {
                unsigned m = __ballot_sync(0xffffffffu, vv[cc] != 0u);
                if (m == 0u) continue;
                if (vv[cc] != 0u) {
                    unsigned pos = cnt + (unsigned)__popc(m & ((1u << lane) - 1u));
                    if (pos < ROWCAP) lp[pos] = (unsigned short)(idx4 + cc);
                }
                cnt += (unsigned)__popc(m);   // warp-uniform update
            }
        }
    }

    if (lane == 0u) g_rowcnt[r] = (cnt > ROWCAP) ? ROWCAP : cnt;
    __threadfence();     // every lane orders its own slot stores
    __syncwarp();        // all lanes' fences done before the release below
    if (lane == 0u) atomicAdd(&g_rows_done[r / EE], 1u);   // release progress
}

// ---------------- consumer role: 29 sequential SIR steps ----------------
__device__ void do_sim(const float* __restrict__ beta,
                       const float* __restrict__ gamma,
                       float* __restrict__ out) {
    const int tid   = threadIdx.x;
    const int gidx  = blockIdx.x * TPB + tid;        // 0 .. NSIM*TPB-1
    const int GS    = NSIM * TPB;
    const int gwarp = gidx >> 5;                     // 0 .. NSIM*8-1
    const int NW    = NSIM * WPB;
    const unsigned lane = (unsigned)tid & 31u;
    unsigned gen = 0;

    for (int t = 0; t < TT; t++) {
        // wait until extraction finished all EE rows of step t
        if (tid == 0) {
            while (atomicAdd(&g_rows_done[t], 0u) < (unsigned)EE) __nanosleep(256);
        }
        __syncthreads();
        __threadfence();                             // acquire list writes

        // phase A (fused SpMV pair, warp-per-edge):
        //   y_e = popcount(ballot(inf[n] != 0))  -- inf is 0/1, exact
        //   then z[n] += y_e for every n in row e.
        for (int e = gwarp; e < EE; e += NW) {
            unsigned r = (unsigned)t * EE + (unsigned)e;
            unsigned c = g_rowcnt[r];
            const unsigned short* lp = g_list + (size_t)r * ROWCAP;
            unsigned isum = 0u;
            for (unsigned i0 = 0; i0 < c; i0 += 32) {
                unsigned i = i0 + lane;
                bool inf = (i < c) && (g_inf[lp[i]] != 0.0f);
                isum += (unsigned)__popc(__ballot_sync(0xffffffffu, inf));
            }
            if (isum != 0u) {
                float ysum = (float)isum;            // small integer: exact
                for (unsigned i0 = 0; i0 < c; i0 += 32) {
                    unsigned i = i0 + lane;
                    if (i < c) atomicAdd(&g_z[lp[i]], ysum);
                }
            }
        }
        sim_barrier(gen);

        // phase B: node update (probabilities + stochastic state machine)
        for (int n = gidx; n < NN; n += GS) {
            float z = g_z[n];
            g_z[n] = 0.0f;

            const size_t PROW = (size_t)t * NN * 3 + (size_t)n * 3;
            const size_t SROW = (size_t)(30 + t) * NN * 3 + (size_t)n * 3;
            float pp0 = out[PROW + 0], pp1 = out[PROW + 1], pp2 = out[PROW + 2];
            float s0  = out[SROW + 0], s1  = out[SROW + 1];

            // Exact-rounding chain, no fmad contraction (matches XLA)
            float nc = __fmul_rn(beta[n],  z);
            float nr = __fmul_rn(gamma[n], s1);
            float p0 = __fsub_rn(pp0, nc);
            float p1 = __fsub_rn(__fadd_rn(pp1, nc), nr);
            float p2 = __fadd_rn(pp2, nr);
            p0 = fminf(fmaxf(p0, 0.0f), 1.0f);
            p1 = fminf(fmaxf(p1, 0.0f), 1.0f);
            p2 = fminf(fmaxf(p2, 0.0f), 1.0f);

            size_t POUT = (size_t)(t + 1) * NN * 3 + (size_t)n * 3;
            out[POUT + 0] = p0; out[POUT + 1] = p1; out[POUT + 2] = p2;

            uint2 k1 = g_k1[t], k2 = g_k2[t];
            unsigned o0, o1;
            tf2x32(k1.x, k1.y, 0u, (unsigned)n, o0, o1);
            float u1 = bits_to_uniform(o0 ^ o1);
            tf2x32(k2.x, k2.y, 0u, (unsigned)n, o0, o1);
            float u2 = bits_to_uniform(o0 ^ o1);

            bool wasS   = (s0 == 1.0f);
            bool wasI   = (s1 == 1.0f);
            bool s_to_I = wasS && (u1 < p1);
            bool i_ev   = wasI && (u1 < p2);
            bool i_to_R = i_ev && (u2 < 0.5f);
            bool i_to_S = i_ev && !(u2 < 0.5f);
            bool nS = (wasS && !s_to_I) || i_to_S;
            bool nI = s_to_I || (wasI && !i_ev);
            bool nR = (!wasS && !wasI) || i_to_R;

            size_t SOUT = (size_t)(30 + t + 1) * NN * 3 + (size_t)n * 3;
            float fI = nI ? 1.0f : 0.0f;
            out[SOUT + 0] = nS ? 1.0f : 0.0f;
            out[SOUT + 1] = fI;
            out[SOUT + 2] = nR ? 1.0f : 0.0f;
            g_inf[n] = fI;
        }
        sim_barrier(gen);   // inf/z visible before next step's phase A
    }
}

// ---------------- fused kernel: sim blocks persistent, extraction blocks wave ----
// Sim blocks are bids 0..NSIM-1 (scheduled first => guaranteed resident).
// Extraction blocks do one row per warp and exit; they never wait on sim.
__global__ void __launch_bounds__(TPB, 4)
k_fused(const float* __restrict__ H,
        const float* __restrict__ beta,
        const float* __restrict__ gamma,
        float* __restrict__ out) {
    if (blockIdx.x < NSIM) do_sim(beta, gamma, out);
    else                   do_extract(H);
}

// ---------------- launch ----------------
extern "C" void kernel_launch(void* const* d_in, const int* in_sizes, int n_in,
                              void* d_out, int out_size) {
    const float* x     = (const float*)d_in[0];  // (N,3)
    const float* H     = (const float*)d_in[1];  // (29, E, N)
    const float* beta  = (const float*)d_in[2];  // (N,)
    const float* gamma = (const float*)d_in[3];  // (N,)
    float* out = (float*)d_out;                  // pathogen (30,N,3) then state (30,N,3)

    (void)in_sizes; (void)n_in; (void)out_size;

    k_init<<<(NN * 3 + 127) / 128, 128>>>(x, out);
    k_fused<<<NBLK, TPB>>>(H, beta, gamma, out);
}

// round 13
// speedup vs baseline: 1.1883x; 1.1883x over previous
#include <cuda_runtime.h>
#include <stdint.h>

// Problem constants (fixed by the dataset)
#define NN      10000      // nodes
#define EE      1000       // hyperedges
#define TT      29         // STEPS - 1 transition steps
#define NROWS   (TT * EE)  // 29000 H rows
#define ROWCAP  64         // per-row nonzero capacity (Binom(10000,0.001): P(>64)~0)
#define NSIM    16         // sim blocks (bids 0..15)
#define NEXTB   280        // extraction blocks (2 per SM)
#define NBLK    (NSIM + NEXTB)
#define TPB     256
#define ROWBYTES (NN * 4)          // 40000 bytes per H row (16B multiple)
#define ROWU4    (NN / 4)          // 2500 uint4 per row
#define BUFSTRIDE 40960            // smem buffer stride (1KB aligned)
#define DSMEM    (2 * BUFSTRIDE)   // dynamic smem per block: 81920 B

// ---------------- device scratch (no allocations allowed) ----------------
__device__ unsigned short g_list[(size_t)NROWS * ROWCAP]; // node ids per row
__device__ unsigned g_rowcnt[NROWS];   // nonzeros per row
__device__ float    g_z[NN];           // z = H^T (H @ infected)
__device__ float    g_inf[NN];         // infected vector (0/1)
__device__ uint2    g_k1[TT];          // per-step uniform keys (u1)
__device__ uint2    g_k2[TT];          // per-step uniform keys (u2)
__device__ unsigned g_rows_done[TT];   // extraction progress per step (release flag)
__device__ unsigned g_bar_cnt;         // sim grid barrier: arrivals (monotonic)
__device__ unsigned g_bar_gen;         // sim grid barrier: released generation

// ---------------- PTX helpers: mbarrier + 1D bulk async copy ----------------
__device__ __forceinline__ unsigned smem_u32(const void* p) {
    return (unsigned)__cvta_generic_to_shared(p);
}
__device__ __forceinline__ void mbar_init(unsigned mb, unsigned count) {
    asm volatile("mbarrier.init.shared.b64 [%0], %1;" :: "r"(mb), "r"(count) : "memory");
}
__device__ __forceinline__ void mbar_expect_tx(unsigned mb, unsigned bytes) {
    asm volatile("mbarrier.arrive.expect_tx.shared.b64 _, [%0], %1;"
                 :: "r"(mb), "r"(bytes) : "memory");
}
__device__ __forceinline__ void bulk_g2s(unsigned dst, const void* src,
                                         unsigned bytes, unsigned mb) {
    asm volatile("cp.async.bulk.shared::cluster.global.mbarrier::complete_tx::bytes "
                 "[%0], [%1], %2, [%3];"
                 :: "r"(dst), "l"(src), "r"(bytes), "r"(mb) : "memory");
}
__device__ __forceinline__ void mbar_wait(unsigned mb, unsigned parity) {
    unsigned done;
    asm volatile("{\n\t.reg .pred p;\n\t"
                 "mbarrier.try_wait.parity.acquire.cta.shared::cta.b64 p, [%1], %2;\n\t"
                 "selp.b32 %0, 1, 0, p;\n\t}"
                 : "=r"(done) : "r"(mb), "r"(parity) : "memory");
    if (!done) {
        asm volatile("{\n\t.reg .pred P1;\n\t"
                     "W%=:\n\t"
                     "mbarrier.try_wait.parity.acquire.cta.shared::cta.b64 P1, [%0], %1, 0x989680;\n\t"
                     "@P1 bra.uni D%=;\n\t"
                     "bra.uni W%=;\n\t"
                     "D%=:\n\t}"
                     :: "r"(mb), "r"(parity) : "memory");
    }
}

// ---------------- JAX Threefry-2x32 (exact replica) ----------------
__device__ __forceinline__ void tf2x32(unsigned k0, unsigned k1,
                                       unsigned x0, unsigned x1,
                                       unsigned &o0, unsigned &o1) {
    unsigned ks2 = k0 ^ k1 ^ 0x1BD11BDAu;
    x0 += k0; x1 += k1;
#define ROTL(v,d) (((v) << (d)) | ((v) >> (32 - (d))))
#define RND(r) { x0 += x1; x1 = ROTL(x1, r); x1 ^= x0; }
    RND(13) RND(15) RND(26) RND(6)
    x0 += k1;  x1 += ks2 + 1u;
    RND(17) RND(29) RND(16) RND(24)
    x0 += ks2; x1 += k0 + 2u;
    RND(13) RND(15) RND(26) RND(6)
    x0 += k0;  x1 += k1 + 3u;
    RND(17) RND(29) RND(16) RND(24)
    x0 += k1;  x1 += ks2 + 4u;
    RND(13) RND(15) RND(26) RND(6)
    x0 += ks2; x1 += k0 + 5u;
    o0 = x0; o1 = x1;
#undef RND
#undef ROTL
}

__device__ __forceinline__ float bits_to_uniform(unsigned bits) {
    return __uint_as_float((bits >> 9) | 0x3F800000u) - 1.0f;
}

// ---------------- init: copy t=0 rows, key chain, reset all scratch ----------------
__global__ void k_init(const float* __restrict__ x, float* __restrict__ out) {
    int gid = blockIdx.x * blockDim.x + threadIdx.x;
    if (gid < NN * 3) {
        float v = x[gid];
        out[gid] = v;                                 // pathogen[0] = x
        out[(size_t)30 * NN * 3 + gid] = v;           // state[0]    = x
    }
    if (gid < NN) {
        g_z[gid]   = 0.0f;
        g_inf[gid] = x[gid * 3 + 1];
    }
    if (gid < TT) g_rows_done[gid] = 0u;
    if (gid == 0) {
        g_bar_cnt = 0u; g_bar_gen = 0u;
        // key chain: jax.random.key(42) -> (0, 42); partitionable split:
        // key_i = threefry(key, (0, i)) full output; new carry = i=0.
        unsigned kh = 0u, kl = 42u;
        for (int t = 0; t < TT; t++) {
            unsigned a0, a1, b0, b1, c0, c1;
            tf2x32(kh, kl, 0u, 0u, a0, a1);
            tf2x32(kh, kl, 0u, 1u, b0, b1);
            tf2x32(kh, kl, 0u, 2u, c0, c1);
            g_k1[t] = make_uint2(b0, b1);
            g_k2[t] = make_uint2(c0, c1);
            kh = a0; kl = a1;
        }
    }
}

// ---------------- sim-side grid barrier (NSIM blocks, busy spin) ----------------
__device__ __forceinline__ void sim_barrier(unsigned &gen) {
    __syncthreads();
    gen += 1u;
    if (threadIdx.x == 0) {
        __threadfence();                                   // release my writes
        unsigned a = atomicAdd(&g_bar_cnt, 1u) + 1u;
        if (a == gen * NSIM) {
            atomicExch(&g_bar_gen, gen);                   // release generation
        } else {
            while (atomicAdd(&g_bar_gen, 0u) < gen) { }    // ~320cyc poll, 16 pollers
        }
        __threadfence();                                   // acquire others' writes
    }
    __syncthreads();
}

// ---------------- producer role: bulk-async double-buffered row extraction -----
// cp.async.bulk streams each 40KB row into smem (UBLKCP: no scoreboards, no
// L1tex wavefronts, hits the LTS cap); 256 threads scan from smem and compact
// via one shared atomic counter (list order is irrelevant to the consumer).
__device__ void do_extract(const float* __restrict__ H, char* sm) {
    __shared__ __align__(8) unsigned long long mbar_s[2];
    __shared__ unsigned s_cnt;
    const int tid = threadIdx.x;
    const int b   = (int)blockIdx.x - NSIM;           // 0..NEXTB-1
    const unsigned mb0 = smem_u32(&mbar_s[0]);
    const unsigned mb1 = smem_u32(&mbar_s[1]);
    const unsigned buf0 = smem_u32(sm);
    const unsigned buf1 = smem_u32(sm + BUFSTRIDE);
    const uint4* bufp[2] = { (const uint4*)sm, (const uint4*)(sm + BUFSTRIDE) };

    if (tid == 0) {
        mbar_init(mb0, 1u);
        mbar_init(mb1, 1u);
        s_cnt = 0u;
    }
    __syncthreads();

    const int nmine = (NROWS - 1 - b) / NEXTB + 1;    // rows this block owns (103/104)

    // prologue: issue rows 0 and 1 of my set
    if (tid == 0) {
        mbar_expect_tx(mb0, ROWBYTES);
        bulk_g2s(buf0, H + (size_t)b * NN, ROWBYTES, mb0);
        if (nmine > 1) {
            mbar_expect_tx(mb1, ROWBYTES);
            bulk_g2s(buf1, H + (size_t)(b + NEXTB) * NN, ROWBYTES, mb1);
        }
    }

    unsigned phase[2] = {0u, 0u};
    for (int k = 0; k < nmine; k++) {
        const int r  = b + k * NEXTB;
        const int cb = k & 1;
        mbar_wait(cb ? mb1 : mb0, phase[cb]);         // every thread waits
        phase[cb] ^= 1u;

        // scan smem buffer; H bits are 0x0 / 0x3F800000 -> integer tests exact
        const uint4* buf = bufp[cb];
        unsigned short* lp = g_list + (size_t)r * ROWCAP;
#pragma unroll
        for (int kk = 0; kk < 10; kk++) {
            int idx = kk * TPB + tid;
            if (idx >= ROWU4) break;
            uint4 v = buf[idx];
            if ((v.x | v.y | v.z | v.w) == 0u) continue;   // ~90% skip
            unsigned vv[4] = {v.x, v.y, v.z, v.w};
#pragma unroll
            for (int cc = 0; cc < 4; cc++) {
                if (vv[cc] != 0u) {
                    unsigned pos = atomicAdd(&s_cnt, 1u);  // ~10/row: no contention
                    if (pos < ROWCAP) lp[pos] = (unsigned short)(idx * 4 + cc);
                }
            }
        }
        __threadfence();            // order my g_list stores
        __syncthreads();            // scan + fences complete block-wide
        if (tid == 0) {
            unsigned c = s_cnt; if (c > ROWCAP) c = ROWCAP;
            g_rowcnt[r] = c;
            s_cnt = 0u;
            __threadfence();
            atomicAdd(&g_rows_done[r / EE], 1u);       // release step progress
        }
        __syncthreads();            // s_cnt reset visible before next scan
        // refill this buffer with row k+2
        if (tid == 0 && k + 2 < nmine) {
            int r2 = b + (k + 2) * NEXTB;
            mbar_expect_tx(cb ? mb1 : mb0, ROWBYTES);
            bulk_g2s(cb ? buf1 : buf0, H + (size_t)r2 * NN, ROWBYTES, cb ? mb1 : mb0);
        }
    }
}

// ---------------- consumer role: 29 sequential SIR steps ----------------
__device__ void do_sim(const float* __restrict__ beta,
                       const float* __restrict__ gamma,
                       float* __restrict__ out) {
    const int tid  = threadIdx.x;
    const int gidx = blockIdx.x * TPB + tid;         // 0 .. NSIM*TPB-1
    const int GS   = NSIM * TPB;                     // 4096
    unsigned gen = 0;

    for (int t = 0; t < TT; t++) {
        // wait until extraction finished all EE rows of step t
        if (tid == 0) {
            while (atomicAdd(&g_rows_done[t], 0u) < (unsigned)EE) __nanosleep(128);
        }
        __syncthreads();
        __threadfence();                             // acquire list writes

        // phase A (fused SpMV pair, THREAD-per-edge: all 1000 edges in flight):
        //   y_e = sum inf over row e (0/1 ints, exact), then z[n] += y_e.
        for (int e = gidx; e < EE; e += GS) {
            unsigned r = (unsigned)t * EE + (unsigned)e;
            unsigned c = g_rowcnt[r];
            const unsigned short* lp = g_list + (size_t)r * ROWCAP;
            float ysum = 0.0f;
#pragma unroll 4
            for (unsigned i = 0; i < c; i++) ysum += g_inf[lp[i]];
            if (ysum != 0.0f) {
#pragma unroll 4
                for (unsigned i = 0; i < c; i++) atomicAdd(&g_z[lp[i]], ysum);
            }
        }
        sim_barrier(gen);

        // phase B: node update (probabilities + stochastic state machine)
        for (int n = gidx; n < NN; n += GS) {
            float z = g_z[n];
            g_z[n] = 0.0f;

            const size_t PROW = (size_t)t * NN * 3 + (size_t)n * 3;
            const size_t SROW = (size_t)(30 + t) * NN * 3 + (size_t)n * 3;
            float pp0 = out[PROW + 0], pp1 = out[PROW + 1], pp2 = out[PROW + 2];
            float s0  = out[SROW + 0], s1  = out[SROW + 1];

            // Exact-rounding chain, no fmad contraction (matches XLA)
            float nc = __fmul_rn(beta[n],  z);
            float nr = __fmul_rn(gamma[n], s1);
            float p0 = __fsub_rn(pp0, nc);
            float p1 = __fsub_rn(__fadd_rn(pp1, nc), nr);
            float p2 = __fadd_rn(pp2, nr);
            p0 = fminf(fmaxf(p0, 0.0f), 1.0f);
            p1 = fminf(fmaxf(p1, 0.0f), 1.0f);
            p2 = fminf(fmaxf(p2, 0.0f), 1.0f);

            size_t POUT = (size_t)(t + 1) * NN * 3 + (size_t)n * 3;
            out[POUT + 0] = p0; out[POUT + 1] = p1; out[POUT + 2] = p2;

            uint2 k1 = g_k1[t], k2 = g_k2[t];
            unsigned o0, o1;
            tf2x32(k1.x, k1.y, 0u, (unsigned)n, o0, o1);
            float u1 = bits_to_uniform(o0 ^ o1);
            tf2x32(k2.x, k2.y, 0u, (unsigned)n, o0, o1);
            float u2 = bits_to_uniform(o0 ^ o1);

            bool wasS   = (s0 == 1.0f);
            bool wasI   = (s1 == 1.0f);
            bool s_to_I = wasS && (u1 < p1);
            bool i_ev   = wasI && (u1 < p2);
            bool i_to_R = i_ev && (u2 < 0.5f);
            bool i_to_S = i_ev && !(u2 < 0.5f);
            bool nS = (wasS && !s_to_I) || i_to_S;
            bool nI = s_to_I || (wasI && !i_ev);
            bool nR = (!wasS && !wasI) || i_to_R;

            size_t SOUT = (size_t)(30 + t + 1) * NN * 3 + (size_t)n * 3;
            float fI = nI ? 1.0f : 0.0f;
            out[SOUT + 0] = nS ? 1.0f : 0.0f;
            out[SOUT + 1] = fI;
            out[SOUT + 2] = nR ? 1.0f : 0.0f;
            g_inf[n] = fI;
        }
        sim_barrier(gen);   // inf/z visible before next step's phase A
    }
}

// ---------------- fused persistent kernel ----------------
// 296 blocks = 2 per SM exactly (81920B dyn smem each, <=128 regs): all blocks
// co-resident, so producer/consumer handshakes cannot deadlock.
__global__ void __launch_bounds__(TPB, 2)
k_fused(const float* __restrict__ H,
        const float* __restrict__ beta,
        const float* __restrict__ gamma,
        float* __restrict__ out) {
    extern __shared__ char sm[];
    if (blockIdx.x < NSIM) do_sim(beta, gamma, out);
    else                   do_extract(H, sm);
}

// ---------------- launch ----------------
extern "C" void kernel_launch(void* const* d_in, const int* in_sizes, int n_in,
                              void* d_out, int out_size) {
    const float* x     = (const float*)d_in[0];  // (N,3)
    const float* H     = (const float*)d_in[1];  // (29, E, N)
    const float* beta  = (const float*)d_in[2];  // (N,)
    const float* gamma = (const float*)d_in[3];  // (N,)
    float* out = (float*)d_out;                  // pathogen (30,N,3) then state (30,N,3)

    (void)in_sizes; (void)n_in; (void)out_size;

    static int attr_done = 0;
    if (!attr_done) {
        cudaFuncSetAttribute(k_fused, cudaFuncAttributeMaxDynamicSharedMemorySize, DSMEM);
        attr_done = 1;
    }

    k_init<<<(NN * 3 + 127) / 128, 128>>>(x, out);
    k_fused<<<NBLK, TPB, DSMEM>>>(H, beta, gamma, out);
}

// round 14
// speedup vs baseline: 1.3115x; 1.1037x over previous
#include <cuda_runtime.h>
#include <stdint.h>

// Problem constants (fixed by the dataset)
#define NN      10000      // nodes
#define EE      1000       // hyperedges
#define TT      29         // STEPS - 1 transition steps
#define NROWS   (TT * EE)  // 29000 H rows
#define ROWCAP  64         // per-row nonzero capacity (Binom(10000,0.001): P(>64)~0)
#define NSIM    16         // sim blocks (bids 0..15)
#define NEXTB   132        // extraction blocks (1 per SM, sharing with 16 sim SMs)
#define NBLK    (NSIM + NEXTB)   // 148 = one block per SM, all co-resident
#define TPB     128
#define NBUF    4                  // smem row buffers per block, 1 per warp
#define ROWBYTES (NN * 4)          // 40000 bytes per H row (16B multiple)
#define ROWU4    (NN / 4)          // 2500 uint4 per row
#define BUFSTRIDE 40960            // smem buffer stride (1KB aligned)
#define DSMEM    (NBUF * BUFSTRIDE) // 163840 B dynamic smem per block

// ---------------- device scratch (no allocations allowed) ----------------
__device__ unsigned short g_list[(size_t)NROWS * ROWCAP]; // node ids per row
__device__ unsigned g_rowcnt[NROWS];   // nonzeros per row
__device__ float    g_z[NN];           // z = H^T (H @ infected)
__device__ float    g_inf[NN];         // infected vector (0/1)
__device__ uint2    g_k1[TT];          // per-step uniform keys (u1)
__device__ uint2    g_k2[TT];          // per-step uniform keys (u2)
__device__ unsigned g_rows_done[TT];   // extraction progress per step (release flag)
__device__ unsigned g_bar_cnt;         // sim grid barrier: arrivals (monotonic)
__device__ unsigned g_bar_gen;         // sim grid barrier: released generation

// ---------------- PTX helpers: mbarrier + 1D bulk async copy ----------------
__device__ __forceinline__ unsigned smem_u32(const void* p) {
    return (unsigned)__cvta_generic_to_shared(p);
}
__device__ __forceinline__ void mbar_init(unsigned mb, unsigned count) {
    asm volatile("mbarrier.init.shared.b64 [%0], %1;" :: "r"(mb), "r"(count) : "memory");
}
__device__ __forceinline__ void mbar_expect_tx(unsigned mb, unsigned bytes) {
    asm volatile("mbarrier.arrive.expect_tx.shared.b64 _, [%0], %1;"
                 :: "r"(mb), "r"(bytes) : "memory");
}
__device__ __forceinline__ void bulk_g2s(unsigned dst, const void* src,
                                         unsigned bytes, unsigned mb) {
    asm volatile("cp.async.bulk.shared::cluster.global.mbarrier::complete_tx::bytes "
                 "[%0], [%1], %2, [%3];"
                 :: "r"(dst), "l"(src), "r"(bytes), "r"(mb) : "memory");
}
__device__ __forceinline__ void mbar_wait(unsigned mb, unsigned parity) {
    unsigned done;
    asm volatile("{\n\t.reg .pred p;\n\t"
                 "mbarrier.try_wait.parity.acquire.cta.shared::cta.b64 p, [%1], %2;\n\t"
                 "selp.b32 %0, 1, 0, p;\n\t}"
                 : "=r"(done) : "r"(mb), "r"(parity) : "memory");
    if (!done) {
        asm volatile("{\n\t.reg .pred P1;\n\t"
                     "W%=:\n\t"
                     "mbarrier.try_wait.parity.acquire.cta.shared::cta.b64 P1, [%0], %1, 0x989680;\n\t"
                     "@P1 bra.uni D%=;\n\t"
                     "bra.uni W%=;\n\t"
                     "D%=:\n\t}"
                     :: "r"(mb), "r"(parity) : "memory");
    }
}

// ---------------- JAX Threefry-2x32 (exact replica) ----------------
__device__ __forceinline__ void tf2x32(unsigned k0, unsigned k1,
                                       unsigned x0, unsigned x1,
                                       unsigned &o0, unsigned &o1) {
    unsigned ks2 = k0 ^ k1 ^ 0x1BD11BDAu;
    x0 += k0; x1 += k1;
#define ROTL(v,d) (((v) << (d)) | ((v) >> (32 - (d))))
#define RND(r) { x0 += x1; x1 = ROTL(x1, r); x1 ^= x0; }
    RND(13) RND(15) RND(26) RND(6)
    x0 += k1;  x1 += ks2 + 1u;
    RND(17) RND(29) RND(16) RND(24)
    x0 += ks2; x1 += k0 + 2u;
    RND(13) RND(15) RND(26) RND(6)
    x0 += k0;  x1 += k1 + 3u;
    RND(17) RND(29) RND(16) RND(24)
    x0 += k1;  x1 += ks2 + 4u;
    RND(13) RND(15) RND(26) RND(6)
    x0 += ks2; x1 += k0 + 5u;
    o0 = x0; o1 = x1;
#undef RND
#undef ROTL
}

__device__ __forceinline__ float bits_to_uniform(unsigned bits) {
    return __uint_as_float((bits >> 9) | 0x3F800000u) - 1.0f;
}

// ---------------- init: copy t=0 rows, key chain, reset all scratch ----------------
__global__ void k_init(const float* __restrict__ x, float* __restrict__ out) {
    int gid = blockIdx.x * blockDim.x + threadIdx.x;
    if (gid < NN * 3) {
        float v = x[gid];
        out[gid] = v;                                 // pathogen[0] = x
        out[(size_t)30 * NN * 3 + gid] = v;           // state[0]    = x
    }
    if (gid < NN) {
        g_z[gid]   = 0.0f;
        g_inf[gid] = x[gid * 3 + 1];
    }
    if (gid < TT) g_rows_done[gid] = 0u;
    if (gid == 0) {
        g_bar_cnt = 0u; g_bar_gen = 0u;
        // key chain: jax.random.key(42) -> (0, 42); partitionable split:
        // key_i = threefry(key, (0, i)) full output; new carry = i=0.
        unsigned kh = 0u, kl = 42u;
        for (int t = 0; t < TT; t++) {
            unsigned a0, a1, b0, b1, c0, c1;
            tf2x32(kh, kl, 0u, 0u, a0, a1);
            tf2x32(kh, kl, 0u, 1u, b0, b1);
            tf2x32(kh, kl, 0u, 2u, c0, c1);
            g_k1[t] = make_uint2(b0, b1);
            g_k2[t] = make_uint2(c0, c1);
            kh = a0; kl = a1;
        }
    }
}

// ---------------- sim-side grid barrier (NSIM blocks, busy spin) ----------------
__device__ __forceinline__ void sim_barrier(unsigned &gen) {
    __syncthreads();
    gen += 1u;
    if (threadIdx.x == 0) {
        __threadfence();                                   // release my writes
        unsigned a = atomicAdd(&g_bar_cnt, 1u) + 1u;
        if (a == gen * NSIM) {
            atomicExch(&g_bar_gen, gen);                   // release generation
        } else {
            while (atomicAdd(&g_bar_gen, 0u) < gen) { }    // 16 pollers on one L2 word
        }
        __threadfence();                                   // acquire others' writes
    }
    __syncthreads();
}

// ---------------- producer role: warp-owned deep-ring bulk-async extraction -----
// Each of 4 warps owns one 40KB smem buffer + mbarrier outright: wait copy ->
// warp-collective scan (LDS + ballot compaction) -> release row -> issue refill.
// No block-wide syncs anywhere, so copies from other warps stay in flight while
// any warp scans: the bulk engine keeps 2-3 copies/SM outstanding continuously.
__device__ void do_extract(const float* __restrict__ H, char* sm) {
    __shared__ __align__(8) unsigned long long mbar_s[NBUF];
    const int tid  = threadIdx.x;
    const int w    = tid >> 5;                       // warp id = buffer id (0..3)
    const unsigned lane = (unsigned)tid & 31u;
    const int b    = (int)blockIdx.x - NSIM;         // 0..NEXTB-1
    const unsigned mb  = smem_u32(&mbar_s[w]);
    const unsigned buf = smem_u32(sm + w * BUFSTRIDE);
    const uint4* bufp  = (const uint4*)(sm + w * BUFSTRIDE);

    if (tid < NBUF) mbar_init(smem_u32(&mbar_s[tid]), 1u);
    __syncthreads();                                  // mbarriers ready (only block sync)

    const int nmine = (NROWS - 1 - b) / NEXTB + 1;    // 219 or 220 rows this block

    // prologue: warp w issues the copy for its first row into its own buffer
    if (w < nmine && lane == 0u) {
        mbar_expect_tx(mb, ROWBYTES);
        bulk_g2s(buf, H + (size_t)(b + (size_t)w * NEXTB) * NN, ROWBYTES, mb);
    }

    unsigned phase = 0u;
    for (int k = w; k < nmine; k += NBUF) {
        const int r = b + k * NEXTB;
        mbar_wait(mb, phase);                         // all 32 lanes wait
        phase ^= 1u;

        // warp-collective scan of the 40KB smem row (integer tests exact:
        // H bits are 0x0 / 0x3F800000)
        unsigned short* lp = g_list + (size_t)r * ROWCAP;
        unsigned cnt = 0u;                            // warp-uniform
        for (int i = 0; i < (ROWU4 + 31) / 32; i++) {
            int idx = i * 32 + (int)lane;
            uint4 v = (idx < ROWU4) ? bufp[idx] : make_uint4(0u, 0u, 0u, 0u);
            bool any = (v.x | v.y | v.z | v.w) != 0u;
            if (__ballot_sync(0xffffffffu, any) == 0u) continue;   // ~88% skip
            unsigned vv[4] = {v.x, v.y, v.z, v.w};
#pragma unroll
            for (int cc = 0; cc < 4; cc++) {
                unsigned m = __ballot_sync(0xffffffffu, vv[cc] != 0u);
                if (m == 0u) continue;
                if (vv[cc] != 0u) {
                    unsigned pos = cnt + (unsigned)__popc(m & ((1u << lane) - 1u));
                    if (pos < ROWCAP) lp[pos] = (unsigned short)(idx * 4 + cc);
                }
                cnt += (unsigned)__popc(m);           // warp-uniform update
            }
        }

        __threadfence();       // each lane orders its own g_list stores
        __syncwarp();          // all lanes' scans + fences done
        if (lane == 0u) {
            g_rowcnt[r] = (cnt > ROWCAP) ? ROWCAP : cnt;
            __threadfence();
            atomicAdd(&g_rows_done[r / EE], 1u);      // release step progress
            // refill this warp's buffer with its next row
            if (k + NBUF < nmine) {
                mbar_expect_tx(mb, ROWBYTES);
                bulk_g2s(buf, H + (size_t)(b + (size_t)(k + NBUF) * NEXTB) * NN,
                         ROWBYTES, mb);
            }
        }
    }
}

// ---------------- consumer role: 29 sequential SIR steps ----------------
__device__ void do_sim(const float* __restrict__ beta,
                       const float* __restrict__ gamma,
                       float* __restrict__ out) {
    const int tid  = threadIdx.x;
    const int gidx = blockIdx.x * TPB + tid;         // 0 .. NSIM*TPB-1
    const int GS   = NSIM * TPB;                     // 2048
    unsigned gen = 0;

    for (int t = 0; t < TT; t++) {
        // wait until extraction finished all EE rows of step t
        if (tid == 0) {
            while (atomicAdd(&g_rows_done[t], 0u) < (unsigned)EE) __nanosleep(128);
        }
        __syncthreads();
        __threadfence();                             // acquire list writes

        // phase A (fused SpMV pair, thread-per-edge):
        //   y_e = sum inf over row e (0/1 ints, exact), then z[n] += y_e.
        for (int e = gidx; e < EE; e += GS) {
            unsigned r = (unsigned)t * EE + (unsigned)e;
            unsigned c = g_rowcnt[r];
            const unsigned short* lp = g_list + (size_t)r * ROWCAP;
            float ysum = 0.0f;
#pragma unroll 4
            for (unsigned i = 0; i < c; i++) ysum += g_inf[lp[i]];
            if (ysum != 0.0f) {
#pragma unroll 4
                for (unsigned i = 0; i < c; i++) atomicAdd(&g_z[lp[i]], ysum);
            }
        }
        sim_barrier(gen);

        // phase B: node update (probabilities + stochastic state machine)
        for (int n = gidx; n < NN; n += GS) {
            float z = g_z[n];
            g_z[n] = 0.0f;

            const size_t PROW = (size_t)t * NN * 3 + (size_t)n * 3;
            const size_t SROW = (size_t)(30 + t) * NN * 3 + (size_t)n * 3;
            float pp0 = out[PROW + 0], pp1 = out[PROW + 1], pp2 = out[PROW + 2];
            float s0  = out[SROW + 0], s1  = out[SROW + 1];

            // Exact-rounding chain, no fmad contraction (matches XLA)
            float nc = __fmul_rn(beta[n],  z);
            float nr = __fmul_rn(gamma[n], s1);
            float p0 = __fsub_rn(pp0, nc);
            float p1 = __fsub_rn(__fadd_rn(pp1, nc), nr);
            float p2 = __fadd_rn(pp2, nr);
            p0 = fminf(fmaxf(p0, 0.0f), 1.0f);
            p1 = fminf(fmaxf(p1, 0.0f), 1.0f);
            p2 = fminf(fmaxf(p2, 0.0f), 1.0f);

            size_t POUT = (size_t)(t + 1) * NN * 3 + (size_t)n * 3;
            out[POUT + 0] = p0; out[POUT + 1] = p1; out[POUT + 2] = p2;

            uint2 k1 = g_k1[t], k2 = g_k2[t];
            unsigned o0, o1;
            tf2x32(k1.x, k1.y, 0u, (unsigned)n, o0, o1);
            float u1 = bits_to_uniform(o0 ^ o1);
            tf2x32(k2.x, k2.y, 0u, (unsigned)n, o0, o1);
            float u2 = bits_to_uniform(o0 ^ o1);

            bool wasS   = (s0 == 1.0f);
            bool wasI   = (s1 == 1.0f);
            bool s_to_I = wasS && (u1 < p1);
            bool i_ev   = wasI && (u1 < p2);
            bool i_to_R = i_ev && (u2 < 0.5f);
            bool i_to_S = i_ev && !(u2 < 0.5f);
            bool nS = (wasS && !s_to_I) || i_to_S;
            bool nI = s_to_I || (wasI && !i_ev);
            bool nR = (!wasS && !wasI) || i_to_R;

            size_t SOUT = (size_t)(30 + t + 1) * NN * 3 + (size_t)n * 3;
            float fI = nI ? 1.0f : 0.0f;
            out[SOUT + 0] = nS ? 1.0f : 0.0f;
            out[SOUT + 1] = fI;
            out[SOUT + 2] = nR ? 1.0f : 0.0f;
            g_inf[n] = fI;
        }
        sim_barrier(gen);   // inf/z visible before next step's phase A
    }
}

// ---------------- fused persistent kernel ----------------
// 148 blocks = exactly 1 per SM (163840B dyn smem): all co-resident, so the
// producer/consumer handshake cannot deadlock. Sim = bids 0..15.
__global__ void __launch_bounds__(TPB, 1)
k_fused(const float* __restrict__ H,
        const float* __restrict__ beta,
        const float* __restrict__ gamma,
        float* __restrict__ out) {
    extern __shared__ char sm[];
    if (blockIdx.x < NSIM) do_sim(beta, gamma, out);
    else                   do_extract(H, sm);
}

// ---------------- launch ----------------
extern "C" void kernel_launch(void* const* d_in, const int* in_sizes, int n_in,
                              void* d_out, int out_size) {
    const float* x     = (const float*)d_in[0];  // (N,3)
    const float* H     = (const float*)d_in[1];  // (29, E, N)
    const float* beta  = (const float*)d_in[2];  // (N,)
    const float* gamma = (const float*)d_in[3];  // (N,)
    float* out = (float*)d_out;                  // pathogen (30,N,3) then state (30,N,3)

    (void)in_sizes; (void)n_in; (void)out_size;

    static int attr_done = 0;
    if (!attr_done) {
        cudaFuncSetAttribute(k_fused, cudaFuncAttributeMaxDynamicSharedMemorySize, DSMEM);
        attr_done = 1;
    }

    k_init<<<(NN * 3 + 127) / 128, 128>>>(x, out);
    k_fused<<<NBLK, TPB, DSMEM>>>(H, beta, gamma, out);
}